// round 3
// baseline (speedup 1.0000x reference)
#include <cuda_runtime.h>

// ---------------- problem constants ----------------
#define NMAX 50000
#define EMAX 1600000
#define KDIM 128   // in/hidden feature width

// ---------------- device scratch (no cudaMalloc allowed) ----------------
__device__ float  g_deg [NMAX];
__device__ float  g_dinv[NMAX];
__device__ int    g_cnt [NMAX];
__device__ int    g_off [NMAX];
__device__ int    g_pos [NMAX];
__device__ int    g_src [EMAX];
__device__ int    g_dst [EMAX];
__device__ int2   g_csr [EMAX];            // (src, norm-as-bits), bucketed by dst
__device__ int    g_bsum[256];
__device__ int    g_is64;                  // 1 if edge_index is int64, 0 if int32
__device__ float4 g_h4  [NMAX * KDIM / 4]; // GEMM output / gather input (16B aligned)
__device__ float4 g_x4  [NMAX * KDIM / 4]; // layer activation buffer   (16B aligned)

// ---------------- dtype detection (device-side, deterministic) ----------------
__global__ void k_detect(const void* __restrict__ ei, int n) {
    if (threadIdx.x == 0 && blockIdx.x == 0) {
        const long long* p = (const long long*)ei;
        int ok = 1;
#pragma unroll
        for (int i = 0; i < 16; i++) {
            long long v = p[i];
            if (v < 0 || v >= (long long)n) ok = 0;
        }
        g_is64 = ok;
    }
}

// ---------------- setup kernels ----------------
__global__ void k_init(int n) {
    int i = blockIdx.x * blockDim.x + threadIdx.x;
    if (i < n) { g_deg[i] = 1.0f; g_cnt[i] = 0; }   // deg starts at 1 (self-loop weight)
}

__global__ void k_edge_deg(const void* __restrict__ ei,
                           const float* __restrict__ ew, int E, int n) {
    int e = blockIdx.x * blockDim.x + threadIdx.x;
    if (e >= E) return;
    int s, d;
    if (g_is64) {
        const long long* p = (const long long*)ei;
        s = (int)p[e]; d = (int)p[E + e];
    } else {
        const int* p = (const int*)ei;
        s = p[e]; d = p[E + e];
    }
    if ((unsigned)s >= (unsigned)n || (unsigned)d >= (unsigned)n) { g_src[e] = 0; g_dst[e] = 0; return; }
    g_src[e] = s; g_dst[e] = d;
    atomicAdd(&g_deg[d], ew[e]);
    atomicAdd(&g_cnt[d], 1);
}

__global__ void k_dinv(int n) {
    int i = blockIdx.x * blockDim.x + threadIdx.x;
    if (i < n) g_dinv[i] = rsqrtf(g_deg[i]);
}

// --- hierarchical exclusive scan of g_cnt -> g_off (chunk = 512) ---
__global__ void k_scan_reduce(int n) {
    __shared__ int s[512];
    int t = threadIdx.x, i = blockIdx.x * 512 + t;
    s[t] = (i < n) ? g_cnt[i] : 0;
    __syncthreads();
    for (int st = 256; st > 0; st >>= 1) {
        if (t < st) s[t] += s[t + st];
        __syncthreads();
    }
    if (t == 0) g_bsum[blockIdx.x] = s[0];
}

__global__ void k_scan_top(int nb) {
    if (threadIdx.x == 0) {
        int run = 0;
        for (int i = 0; i < nb; i++) { int v = g_bsum[i]; g_bsum[i] = run; run += v; }
    }
}

__global__ void k_scan_chunks(int n) {
    __shared__ int s[512];
    int t = threadIdx.x, i = blockIdx.x * 512 + t;
    int v = (i < n) ? g_cnt[i] : 0;
    s[t] = v;
    __syncthreads();
    for (int st = 1; st < 512; st <<= 1) {
        int add = (t >= st) ? s[t - st] : 0;
        __syncthreads();
        s[t] += add;
        __syncthreads();
    }
    if (i < n) {
        int ex = s[t] - v + g_bsum[blockIdx.x];
        g_off[i] = ex;
        g_pos[i] = ex;
    }
}

__global__ void k_edge_fill(const float* __restrict__ ew, int E) {
    int e = blockIdx.x * blockDim.x + threadIdx.x;
    if (e >= E) return;
    int s = g_src[e], d = g_dst[e];
    float nrm = g_dinv[s] * ew[e] * g_dinv[d];
    int p = atomicAdd(&g_pos[d], 1);
    g_csr[p] = make_int2(s, __float_as_int(nrm));
}

// ---------------- dense GEMM: g_h[M,BN] = A[M,128] @ W[128,BN] ----------------
// BM=64, BK=16, 256 threads, thread tile 8x(BN/32)
template<int BN, bool FROM_GX>
__global__ void __launch_bounds__(256)
k_gemm(const float* __restrict__ Ain, const float* __restrict__ W, int M) {
    constexpr int K = KDIM;
    constexpr int BM = 64, BK = 16;
    constexpr int TM = 8, TN = BN / 32;
    __shared__ float As[BK][BM];
    __shared__ float Bs[BK][BN];

    const float* A = FROM_GX ? (const float*)g_x4 : Ain;
    float*       C = (float*)g_h4;

    int tid = threadIdx.x;
    int rb  = blockIdx.x * BM;
    int tc  = tid & 31;   // 0..31 column group
    int tr  = tid >> 5;   // 0..7  row group

    float acc[TM][TN];
#pragma unroll
    for (int i = 0; i < TM; i++)
#pragma unroll
        for (int j = 0; j < TN; j++) acc[i][j] = 0.0f;

    for (int k0 = 0; k0 < K; k0 += BK) {
        // A tile: 64 rows x 16 k (transposed into smem)
        {
            int row = tid >> 2;
            int kq  = (tid & 3) * 4;
            float4 v = make_float4(0.f, 0.f, 0.f, 0.f);
            int gr = rb + row;
            if (gr < M) v = *(const float4*)(A + (long)gr * K + k0 + kq);
            As[kq + 0][row] = v.x; As[kq + 1][row] = v.y;
            As[kq + 2][row] = v.z; As[kq + 3][row] = v.w;
        }
        // W tile: 16 x BN
        {
            constexpr int ITER = (BK * BN) / (256 * 4);
#pragma unroll
            for (int it = 0; it < ITER; it++) {
                int idx = (tid + it * 256) * 4;
                int kk = idx / BN, col = idx % BN;
                *(float4*)(&Bs[kk][col]) = *(const float4*)(W + (long)(k0 + kk) * BN + col);
            }
        }
        __syncthreads();
#pragma unroll
        for (int kk = 0; kk < BK; kk++) {
            float a[TM], b[TN];
#pragma unroll
            for (int i = 0; i < TM; i++) a[i] = As[kk][tr * TM + i];
#pragma unroll
            for (int j = 0; j < TN; j++) b[j] = Bs[kk][tc * TN + j];
#pragma unroll
            for (int i = 0; i < TM; i++)
#pragma unroll
                for (int j = 0; j < TN; j++) acc[i][j] += a[i] * b[j];
        }
        __syncthreads();
    }
#pragma unroll
    for (int i = 0; i < TM; i++) {
        int gr = rb + tr * TM + i;
        if (gr < M) {
#pragma unroll
            for (int j = 0; j < TN; j++)
                C[(long)gr * BN + tc * TN + j] = acc[i][j];
        }
    }
}

// ---------------- sparse aggregation (CSR gather, no atomics) ----------------
// out[i] = relu?( sum_{e: dst=i} h[src_e]*norm_e + h[i]*dinv[i]^2 + bias )
template<int F, bool RELU, bool TO_GX>
__global__ void k_gather(const float* __restrict__ bias,
                         float* __restrict__ outp, int n) {
    constexpr int LPN = F / 4;    // float4 lanes per node (32 for F=128, 16 for F=64)
    int gt   = blockIdx.x * blockDim.x + threadIdx.x;
    int node = gt / LPN;
    int lane = gt % LPN;
    if (node >= n) return;

    float di = g_dinv[node];
    float sl = di * di;
    float4 acc = g_h4[(long)node * LPN + lane];
    acc.x *= sl; acc.y *= sl; acc.z *= sl; acc.w *= sl;

    int o = g_off[node];
    int c = g_cnt[node];
    for (int k = 0; k < c; k++) {
        int2 sp = g_csr[o + k];
        float nrm = __int_as_float(sp.y);
        float4 hv = g_h4[(long)sp.x * LPN + lane];
        acc.x += hv.x * nrm;
        acc.y += hv.y * nrm;
        acc.z += hv.z * nrm;
        acc.w += hv.w * nrm;
    }
    float4 bv = *(const float4*)(bias + lane * 4);
    acc.x += bv.x; acc.y += bv.y; acc.z += bv.z; acc.w += bv.w;
    if (RELU) {
        acc.x = fmaxf(acc.x, 0.f); acc.y = fmaxf(acc.y, 0.f);
        acc.z = fmaxf(acc.z, 0.f); acc.w = fmaxf(acc.w, 0.f);
    }
    if (TO_GX) {
        g_x4[(long)node * LPN + lane] = acc;
    } else {
        *(float4*)(outp + (long)node * F + lane * 4) = acc;
    }
}

// ---------------- host launcher ----------------
extern "C" void kernel_launch(void* const* d_in, const int* in_sizes, int n_in,
                              void* d_out, int out_size) {
    const float* x  = (const float*)d_in[0];
    const void*  ei = d_in[1];
    const float* ew = (const float*)d_in[2];
    const float* W1 = (const float*)d_in[3];
    const float* b1 = (const float*)d_in[4];
    const float* W2 = (const float*)d_in[5];
    const float* b2 = (const float*)d_in[6];
    const float* W3 = (const float*)d_in[7];
    const float* b3 = (const float*)d_in[8];

    const int n = in_sizes[0] / KDIM;   // 50000
    const int E = in_sizes[2];          // 1600000
    float* outp = (float*)d_out;

    const int TB = 256;
    const int nb_nodes = (n + TB - 1) / TB;
    const int nb_edges = (E + TB - 1) / TB;
    const int nchunk   = (n + 511) / 512;

    // ---- dtype detect + normalization + CSR build ----
    k_detect<<<1, 32>>>(ei, n);
    k_init<<<nb_nodes, TB>>>(n);
    k_edge_deg<<<nb_edges, TB>>>(ei, ew, E, n);
    k_dinv<<<nb_nodes, TB>>>(n);
    k_scan_reduce<<<nchunk, 512>>>(n);
    k_scan_top<<<1, 32>>>(nchunk);
    k_scan_chunks<<<nchunk, 512>>>(n);
    k_edge_fill<<<nb_edges, TB>>>(ew, E);

    const int gemm_blocks   = (n + 63) / 64;
    const int gat128_blocks = (n * 32 + TB - 1) / TB;
    const int gat64_blocks  = (n * 16 + TB - 1) / TB;

    // ---- layer 1: h = x@W1 ; x1 = relu(agg(h) + b1) ----
    k_gemm<128, false><<<gemm_blocks, 256>>>(x, W1, n);
    k_gather<128, true, true><<<gat128_blocks, TB>>>(b1, nullptr, n);

    // ---- layer 2: h = x1@W2 ; x2 = relu(agg(h) + b2) ----
    k_gemm<128, true><<<gemm_blocks, 256>>>(nullptr, W2, n);
    k_gather<128, true, true><<<gat128_blocks, TB>>>(b2, nullptr, n);

    // ---- layer 3: h = x2@W3 ; out = agg(h) + b3  (F=64 propagation) ----
    k_gemm<64, true><<<gemm_blocks, 256>>>(nullptr, W3, n);
    k_gather<64, false, false><<<gat64_blocks, TB>>>(b3, outp, n);
}

// round 4
// speedup vs baseline: 1.0740x; 1.0740x over previous
#include <cuda_runtime.h>
#include <cuda_fp16.h>

// ---------------- problem constants ----------------
#define NMAX 50000
#define EMAX 1600000
#define KDIM 128   // in/hidden feature width

// ---------------- device scratch (no cudaMalloc allowed) ----------------
__device__ float  g_deg [NMAX];
__device__ float  g_dinv[NMAX];
__device__ int    g_cnt [NMAX];
__device__ int    g_off [NMAX];
__device__ int    g_pos [NMAX];
__device__ int    g_src [EMAX];
__device__ int    g_dst [EMAX];
__device__ int2   g_csr [EMAX];            // (src, norm-as-bits), bucketed by dst
__device__ int    g_bsum[256];
__device__ int    g_is64;                  // 1 if edge_index is int64, 0 if int32
__device__ uint4  g_hh4 [NMAX * KDIM / 8]; // half-precision h (16 uint4 per node), 16B aligned
__device__ float4 g_h4  [NMAX * KDIM / 4]; // fp32 h for layer 3 (F=64 used)
__device__ float4 g_x4  [NMAX * KDIM / 4]; // fp32 layer activation buffer

// ---------------- dtype detection (device-side, deterministic) ----------------
__global__ void k_detect(const void* __restrict__ ei, int n) {
    if (threadIdx.x == 0 && blockIdx.x == 0) {
        const long long* p = (const long long*)ei;
        int ok = 1;
#pragma unroll
        for (int i = 0; i < 16; i++) {
            long long v = p[i];
            if (v < 0 || v >= (long long)n) ok = 0;
        }
        g_is64 = ok;
    }
}

// ---------------- setup kernels ----------------
__global__ void k_init(int n) {
    int i = blockIdx.x * blockDim.x + threadIdx.x;
    if (i < n) { g_deg[i] = 1.0f; g_cnt[i] = 0; }   // deg starts at 1 (self-loop weight)
}

__global__ void k_edge_deg(const void* __restrict__ ei,
                           const float* __restrict__ ew, int E, int n) {
    int e = blockIdx.x * blockDim.x + threadIdx.x;
    if (e >= E) return;
    int s, d;
    if (g_is64) {
        const long long* p = (const long long*)ei;
        s = (int)p[e]; d = (int)p[E + e];
    } else {
        const int* p = (const int*)ei;
        s = p[e]; d = p[E + e];
    }
    if ((unsigned)s >= (unsigned)n || (unsigned)d >= (unsigned)n) { g_src[e] = 0; g_dst[e] = 0; return; }
    g_src[e] = s; g_dst[e] = d;
    atomicAdd(&g_deg[d], ew[e]);
    atomicAdd(&g_cnt[d], 1);
}

__global__ void k_dinv(int n) {
    int i = blockIdx.x * blockDim.x + threadIdx.x;
    if (i < n) g_dinv[i] = rsqrtf(g_deg[i]);
}

// --- hierarchical exclusive scan of g_cnt -> g_off (chunk = 512) ---
__global__ void k_scan_reduce(int n) {
    __shared__ int s[512];
    int t = threadIdx.x, i = blockIdx.x * 512 + t;
    s[t] = (i < n) ? g_cnt[i] : 0;
    __syncthreads();
    for (int st = 256; st > 0; st >>= 1) {
        if (t < st) s[t] += s[t + st];
        __syncthreads();
    }
    if (t == 0) g_bsum[blockIdx.x] = s[0];
}

__global__ void k_scan_top(int nb) {
    if (threadIdx.x == 0) {
        int run = 0;
        for (int i = 0; i < nb; i++) { int v = g_bsum[i]; g_bsum[i] = run; run += v; }
    }
}

__global__ void k_scan_chunks(int n) {
    __shared__ int s[512];
    int t = threadIdx.x, i = blockIdx.x * 512 + t;
    int v = (i < n) ? g_cnt[i] : 0;
    s[t] = v;
    __syncthreads();
    for (int st = 1; st < 512; st <<= 1) {
        int add = (t >= st) ? s[t - st] : 0;
        __syncthreads();
        s[t] += add;
        __syncthreads();
    }
    if (i < n) {
        int ex = s[t] - v + g_bsum[blockIdx.x];
        g_off[i] = ex;
        g_pos[i] = ex;
    }
}

__global__ void k_edge_fill(const float* __restrict__ ew, int E) {
    int e = blockIdx.x * blockDim.x + threadIdx.x;
    if (e >= E) return;
    int s = g_src[e], d = g_dst[e];
    float nrm = g_dinv[s] * ew[e] * g_dinv[d];
    int p = atomicAdd(&g_pos[d], 1);
    g_csr[p] = make_int2(s, __float_as_int(nrm));
}

// ---------------- dense GEMM: h[M,BN] = A[M,128] @ W[128,BN] ----------------
// BM=128, BK=16, 256 threads, 8x8 (BN=128) or 8x4 (BN=64) microtile.
// HALF_OUT: store half features to g_hh4; else fp32 to g_h4.
template<int BN, bool FROM_GX, bool HALF_OUT>
__global__ void __launch_bounds__(256)
k_gemm(const float* __restrict__ Ain, const float* __restrict__ W, int M) {
    constexpr int K  = KDIM;
    constexpr int BM = 128, BK = 16;
    constexpr int TM = 8;
    constexpr int TN = BN / 16;            // 8 for BN=128, 4 for BN=64
    __shared__ float As[BK][BM];
    __shared__ float Bs[BK][BN];

    const float* A = FROM_GX ? (const float*)g_x4 : Ain;

    const int tid = threadIdx.x;
    const int rb  = blockIdx.x * BM;
    const int tc  = tid & 15;              // 0..15 column group
    const int tr  = tid >> 4;              // 0..15 row group

    float acc[TM][TN];
#pragma unroll
    for (int i = 0; i < TM; i++)
#pragma unroll
        for (int j = 0; j < TN; j++) acc[i][j] = 0.0f;

    const int arow = tid >> 1;             // 0..127
    const int akq  = (tid & 1) * 8;        // 0 or 8

    for (int k0 = 0; k0 < K; k0 += BK) {
        // A tile: 128 rows x 16 k, transposed into smem
        {
            int gr = rb + arow;
            float4 v0 = make_float4(0.f,0.f,0.f,0.f), v1 = v0;
            if (gr < M) {
                const float* ap = A + (long)gr * K + k0 + akq;
                v0 = *(const float4*)(ap);
                v1 = *(const float4*)(ap + 4);
            }
            As[akq + 0][arow] = v0.x; As[akq + 1][arow] = v0.y;
            As[akq + 2][arow] = v0.z; As[akq + 3][arow] = v0.w;
            As[akq + 4][arow] = v1.x; As[akq + 5][arow] = v1.y;
            As[akq + 6][arow] = v1.z; As[akq + 7][arow] = v1.w;
        }
        // W tile: 16 x BN
        {
            constexpr int ITER = (BK * BN) / (256 * 4);
#pragma unroll
            for (int it = 0; it < ITER; it++) {
                int idx = (tid + it * 256) * 4;
                int kk = idx / BN, col = idx % BN;
                *(float4*)(&Bs[kk][col]) = *(const float4*)(W + (long)(k0 + kk) * BN + col);
            }
        }
        __syncthreads();
#pragma unroll
        for (int kk = 0; kk < BK; kk++) {
            float a[TM], b[TN];
#pragma unroll
            for (int i = 0; i < TM; i++) a[i] = As[kk][tr * TM + i];
#pragma unroll
            for (int j = 0; j < TN; j++) b[j] = Bs[kk][tc * TN + j];
#pragma unroll
            for (int i = 0; i < TM; i++)
#pragma unroll
                for (int j = 0; j < TN; j++) acc[i][j] += a[i] * b[j];
        }
        __syncthreads();
    }

#pragma unroll
    for (int i = 0; i < TM; i++) {
        int gr = rb + tr * TM + i;
        if (gr >= M) continue;
        if (HALF_OUT) {
            // TN==8: 8 floats -> 4 half2 -> one uint4 store
            __half2 p0 = __floats2half2_rn(acc[i][0], acc[i][1]);
            __half2 p1 = __floats2half2_rn(acc[i][2], acc[i][3]);
            __half2 p2 = __floats2half2_rn(acc[i][4], acc[i][5]);
            __half2 p3 = __floats2half2_rn(acc[i][6], acc[i][7]);
            uint4 u;
            u.x = *(unsigned*)&p0; u.y = *(unsigned*)&p1;
            u.z = *(unsigned*)&p2; u.w = *(unsigned*)&p3;
            g_hh4[(long)gr * (KDIM / 8) + tc] = u;
        } else {
            // TN==4: one float4 store to g_h4
            float4 v = make_float4(acc[i][0], acc[i][1], acc[i][2], acc[i][3]);
            g_h4[(long)gr * (BN / 4) + tc] = v;
        }
    }
}

// ---------------- sparse aggregation, fp16 features (F=128) ----------------
// out[i] = relu( sum_e h16[src_e]*norm_e + h16[i]*dinv^2 + bias ), fp32 accum
__global__ void k_gather_h(const float* __restrict__ bias, int n) {
    const int gt   = blockIdx.x * blockDim.x + threadIdx.x;
    const int node = gt >> 5;         // warp per node
    const int lane = gt & 31;         // lane handles features 4*lane..4*lane+3
    if (node >= n) return;

    const uint2* hh = (const uint2*)g_hh4;   // 4 halfs per uint2

    float di = g_dinv[node];
    float sl = di * di;

    uint2 selfv = hh[(long)node * 32 + lane];
    __half2 s0 = *(__half2*)&selfv.x, s1 = *(__half2*)&selfv.y;
    float2 f0 = __half22float2(s0), f1 = __half22float2(s1);
    float ax = f0.x * sl, ay = f0.y * sl, az = f1.x * sl, aw = f1.y * sl;

    const int o = g_off[node];
    const int c = g_cnt[node];
#pragma unroll 4
    for (int k = 0; k < c; k++) {
        int2 sp = g_csr[o + k];
        float nrm = __int_as_float(sp.y);
        uint2 hv = hh[(long)sp.x * 32 + lane];
        __half2 h0 = *(__half2*)&hv.x, h1 = *(__half2*)&hv.y;
        float2 g0 = __half22float2(h0), g1 = __half22float2(h1);
        ax = fmaf(g0.x, nrm, ax);
        ay = fmaf(g0.y, nrm, ay);
        az = fmaf(g1.x, nrm, az);
        aw = fmaf(g1.y, nrm, aw);
    }
    float4 bv = *(const float4*)(bias + lane * 4);
    float4 r;
    r.x = fmaxf(ax + bv.x, 0.f);
    r.y = fmaxf(ay + bv.y, 0.f);
    r.z = fmaxf(az + bv.z, 0.f);
    r.w = fmaxf(aw + bv.w, 0.f);
    g_x4[(long)node * 32 + lane] = r;
}

// ---------------- sparse aggregation, fp32 features (F=64, final layer) ----------------
__global__ void k_gather_f64(const float* __restrict__ bias,
                             float* __restrict__ outp, int n) {
    constexpr int LPN = 16;           // float4 lanes per node
    const int gt   = blockIdx.x * blockDim.x + threadIdx.x;
    const int node = gt / LPN;
    const int lane = gt % LPN;
    if (node >= n) return;

    float di = g_dinv[node];
    float sl = di * di;
    float4 acc = g_h4[(long)node * LPN + lane];
    acc.x *= sl; acc.y *= sl; acc.z *= sl; acc.w *= sl;

    const int o = g_off[node];
    const int c = g_cnt[node];
#pragma unroll 4
    for (int k = 0; k < c; k++) {
        int2 sp = g_csr[o + k];
        float nrm = __int_as_float(sp.y);
        float4 hv = g_h4[(long)sp.x * LPN + lane];
        acc.x = fmaf(hv.x, nrm, acc.x);
        acc.y = fmaf(hv.y, nrm, acc.y);
        acc.z = fmaf(hv.z, nrm, acc.z);
        acc.w = fmaf(hv.w, nrm, acc.w);
    }
    float4 bv = *(const float4*)(bias + lane * 4);
    acc.x += bv.x; acc.y += bv.y; acc.z += bv.z; acc.w += bv.w;
    *(float4*)(outp + (long)node * 64 + lane * 4) = acc;
}

// ---------------- host launcher ----------------
extern "C" void kernel_launch(void* const* d_in, const int* in_sizes, int n_in,
                              void* d_out, int out_size) {
    const float* x  = (const float*)d_in[0];
    const void*  ei = d_in[1];
    const float* ew = (const float*)d_in[2];
    const float* W1 = (const float*)d_in[3];
    const float* b1 = (const float*)d_in[4];
    const float* W2 = (const float*)d_in[5];
    const float* b2 = (const float*)d_in[6];
    const float* W3 = (const float*)d_in[7];
    const float* b3 = (const float*)d_in[8];

    const int n = in_sizes[0] / KDIM;   // 50000
    const int E = in_sizes[2];          // 1600000
    float* outp = (float*)d_out;

    const int TB = 256;
    const int nb_nodes = (n + TB - 1) / TB;
    const int nb_edges = (E + TB - 1) / TB;
    const int nchunk   = (n + 511) / 512;

    // ---- dtype detect + normalization + CSR build ----
    k_detect<<<1, 32>>>(ei, n);
    k_init<<<nb_nodes, TB>>>(n);
    k_edge_deg<<<nb_edges, TB>>>(ei, ew, E, n);
    k_dinv<<<nb_nodes, TB>>>(n);
    k_scan_reduce<<<nchunk, 512>>>(n);
    k_scan_top<<<1, 32>>>(nchunk);
    k_scan_chunks<<<nchunk, 512>>>(n);
    k_edge_fill<<<nb_edges, TB>>>(ew, E);

    const int gemm_blocks   = (n + 127) / 128;
    const int gat128_blocks = (n * 32 + TB - 1) / TB;
    const int gat64_blocks  = (n * 16 + TB - 1) / TB;

    // ---- layer 1: h16 = half(x@W1) ; x1 = relu(agg(h16) + b1) ----
    k_gemm<128, false, true><<<gemm_blocks, 256>>>(x, W1, n);
    k_gather_h<<<gat128_blocks, TB>>>(b1, n);

    // ---- layer 2: h16 = half(x1@W2) ; x2 = relu(agg(h16) + b2) ----
    k_gemm<128, true, true><<<gemm_blocks, 256>>>(nullptr, W2, n);
    k_gather_h<<<gat128_blocks, TB>>>(b2, n);

    // ---- layer 3: h = x2@W3 (fp32) ; out = agg(h) + b3 ----
    k_gemm<64, true, false><<<gemm_blocks, 256>>>(nullptr, W3, n);
    k_gather_f64<<<gat64_blocks, TB>>>(b3, outp, n);
}

// round 5
// speedup vs baseline: 1.1861x; 1.1043x over previous
#include <cuda_runtime.h>
#include <cuda_fp16.h>
#include <mma.h>
using namespace nvcuda;

// ---------------- problem constants ----------------
#define NMAX 50000
#define EMAX 1600000
#define KDIM 128

// ---------------- device scratch ----------------
__device__ float  g_deg [NMAX];
__device__ float  g_dinv[NMAX];
__device__ int    g_cnt [NMAX];
__device__ int    g_off [NMAX];
__device__ int    g_pos [NMAX];
__device__ int    g_src [EMAX];
__device__ int    g_dst [EMAX];
__device__ int2   g_csr [EMAX];              // (src, norm-as-bits), bucketed by dst
__device__ int    g_bsum[256];
__device__ int    g_is64;
__device__ uint4  g_a16 [NMAX * KDIM / 8];   // fp16 activations (GEMM input)
__device__ uint4  g_hh  [NMAX * KDIM / 8];   // fp16 GEMM output (gather input)
__device__ float4 g_h4  [NMAX * KDIM / 4];   // fp32 GEMM output (layer 3)
__device__ uint4  g_w16 [5120];              // fp16 W1(2048) W2(2048) W3(1024) uint4s

// ---------------- fused init + dtype detect ----------------
__global__ void k_init(const void* __restrict__ ei, int n) {
    int i = blockIdx.x * blockDim.x + threadIdx.x;
    if (i < n) { g_deg[i] = 1.0f; g_cnt[i] = 0; }
    if (i == 0) {
        const long long* p = (const long long*)ei;
        int ok = 1;
#pragma unroll
        for (int t = 0; t < 16; t++) {
            long long v = p[t];
            if (v < 0 || v >= (long long)n) ok = 0;
        }
        g_is64 = ok;
    }
}

// ---------------- fp32 -> fp16 conversion: x and all weights ----------------
__device__ inline uint4 pack8(float4 a, float4 b) {
    __half2 h0 = __floats2half2_rn(a.x, a.y), h1 = __floats2half2_rn(a.z, a.w);
    __half2 h2 = __floats2half2_rn(b.x, b.y), h3 = __floats2half2_rn(b.z, b.w);
    uint4 u;
    u.x = *(unsigned*)&h0; u.y = *(unsigned*)&h1;
    u.z = *(unsigned*)&h2; u.w = *(unsigned*)&h3;
    return u;
}

__global__ void k_prep(const float4* __restrict__ x,
                       const float4* __restrict__ W1,
                       const float4* __restrict__ W2,
                       const float4* __restrict__ W3, int n) {
    int i = blockIdx.x * blockDim.x + threadIdx.x;
    int nx = n * 16;                         // uint4 units of x
    if (i < nx) {
        g_a16[i] = pack8(x[2 * i], x[2 * i + 1]);
    } else {
        int j = i - nx;
        if (j < 5120) {
            const float4* src; int jj;
            if (j < 2048)      { src = W1; jj = j; }
            else if (j < 4096) { src = W2; jj = j - 2048; }
            else               { src = W3; jj = j - 4096; }
            g_w16[j] = pack8(src[2 * jj], src[2 * jj + 1]);
        }
    }
}

// ---------------- edge pass 1: degree + counts ----------------
__global__ void k_edge_deg(const void* __restrict__ ei,
                           const float* __restrict__ ew, int E, int n) {
    int e = blockIdx.x * blockDim.x + threadIdx.x;
    if (e >= E) return;
    int s, d;
    if (g_is64) {
        const long long* p = (const long long*)ei;
        s = (int)p[e]; d = (int)p[E + e];
    } else {
        const int* p = (const int*)ei;
        s = p[e]; d = p[E + e];
    }
    if ((unsigned)s >= (unsigned)n || (unsigned)d >= (unsigned)n) { g_src[e] = 0; g_dst[e] = 0; return; }
    g_src[e] = s; g_dst[e] = d;
    atomicAdd(&g_deg[d], ew[e]);
    atomicAdd(&g_cnt[d], 1);
}

// ---------------- scan reduce (+ fused dinv) ----------------
__global__ void k_scan_reduce(int n) {
    __shared__ int s[512];
    int t = threadIdx.x, i = blockIdx.x * 512 + t;
    if (i < n) g_dinv[i] = rsqrtf(g_deg[i]);
    s[t] = (i < n) ? g_cnt[i] : 0;
    __syncthreads();
    for (int st = 256; st > 0; st >>= 1) {
        if (t < st) s[t] += s[t + st];
        __syncthreads();
    }
    if (t == 0) g_bsum[blockIdx.x] = s[0];
}

__global__ void k_scan_top(int nb) {
    if (threadIdx.x == 0) {
        int run = 0;
        for (int i = 0; i < nb; i++) { int v = g_bsum[i]; g_bsum[i] = run; run += v; }
    }
}

__global__ void k_scan_chunks(int n) {
    __shared__ int s[512];
    int t = threadIdx.x, i = blockIdx.x * 512 + t;
    int v = (i < n) ? g_cnt[i] : 0;
    s[t] = v;
    __syncthreads();
    for (int st = 1; st < 512; st <<= 1) {
        int add = (t >= st) ? s[t - st] : 0;
        __syncthreads();
        s[t] += add;
        __syncthreads();
    }
    if (i < n) {
        int ex = s[t] - v + g_bsum[blockIdx.x];
        g_off[i] = ex;
        g_pos[i] = ex;
    }
}

__global__ void k_edge_fill(const float* __restrict__ ew, int E) {
    int e = blockIdx.x * blockDim.x + threadIdx.x;
    if (e >= E) return;
    int s = g_src[e], d = g_dst[e];
    float nrm = g_dinv[s] * ew[e] * g_dinv[d];
    int p = atomicAdd(&g_pos[d], 1);
    g_csr[p] = make_int2(s, __float_as_int(nrm));
}

// ---------------- tensor-core GEMM: C[M,N] = A16[M,128] @ W16[128,N] ----------------
// BM=64 rows/CTA, 8 warps in 4x2 grid, warp tile 16 x (N/2). A in smem; W read
// from global (32KB, L1-resident). Epilogue stages fp32 in smem (aliasing As).
template<int N, bool OUT_HALF>
__global__ void __launch_bounds__(256)
k_hgemm(int woff_u4, int M) {
    constexpr int BM  = 64;
    constexpr int LDA = 136;                   // padded halfs per smem row
    constexpr int WN  = N / 2;                 // warp tile cols (64 or 32)
    constexpr int NT  = WN / 16;               // wmma n-tiles per warp
    constexpr int ABYTES = BM * LDA * 2;
    constexpr int SBYTES = 8 * 16 * WN * 4;
    __shared__ __align__(16) char sraw[(ABYTES > SBYTES) ? ABYTES : SBYTES];
    __half (*As)[LDA] = (__half(*)[LDA])sraw;
    float*  stage     = (float*)sraw;

    const __half* Wg = (const __half*)g_w16 + (long)woff_u4 * 8;

    const int tid  = threadIdx.x;
    const int wid  = tid >> 5, lane = tid & 31;
    const int wrow = wid >> 1, wcol = wid & 1;
    const int rb   = blockIdx.x * BM;

    // load A tile (BM x 128 halfs = BM*16 uint4)
    for (int i = tid; i < BM * 16; i += 256) {
        int r = i >> 4, c = i & 15;
        uint4 v = make_uint4(0u, 0u, 0u, 0u);
        if (rb + r < M) v = g_a16[(long)(rb + r) * 16 + c];
        *(uint4*)&As[r][c * 8] = v;
    }
    __syncthreads();

    wmma::fragment<wmma::accumulator, 16, 16, 16, float> acc[NT];
#pragma unroll
    for (int j = 0; j < NT; j++) wmma::fill_fragment(acc[j], 0.0f);

    wmma::fragment<wmma::matrix_a, 16, 16, 16, __half, wmma::row_major> af;
    wmma::fragment<wmma::matrix_b, 16, 16, 16, __half, wmma::row_major> bf;
#pragma unroll
    for (int k = 0; k < 8; k++) {
        wmma::load_matrix_sync(af, &As[wrow * 16][k * 16], LDA);
#pragma unroll
        for (int j = 0; j < NT; j++) {
            wmma::load_matrix_sync(bf, Wg + (long)(k * 16) * N + wcol * WN + j * 16, N);
            wmma::mma_sync(acc[j], af, bf, acc[j]);
        }
    }
    __syncthreads();   // all warps done reading As before stage aliases it

    float* st = stage + wid * 16 * WN;
#pragma unroll
    for (int j = 0; j < NT; j++)
        wmma::store_matrix_sync(st + j * 16, acc[j], WN, wmma::mem_row_major);
    __syncwarp();

    const int r0 = rb + wrow * 16;
    if (OUT_HALF) {
        unsigned* outh = (unsigned*)g_hh;
        for (int i = lane; i < 16 * WN / 2; i += 32) {
            int r = (i * 2) / WN, c = (i * 2) % WN;
            int gr = r0 + r;
            if (gr < M) {
                __half2 h = __floats2half2_rn(st[r * WN + c], st[r * WN + c + 1]);
                outh[((long)gr * KDIM + wcol * WN + c) >> 1] = *(unsigned*)&h;
            }
        }
    } else {
        float* outf = (float*)g_h4;
        for (int i = lane; i < 16 * WN / 2; i += 32) {
            int r = (i * 2) / WN, c = (i * 2) % WN;
            int gr = r0 + r;
            if (gr < M) {
                float2 v = make_float2(st[r * WN + c], st[r * WN + c + 1]);
                *(float2*)(outf + (long)gr * N + wcol * WN + c) = v;
            }
        }
    }
}

// ---------------- sparse aggregation, fp16 features (F=128) ----------------
// x1[i] = half( relu( sum_e h16[src]*norm + h16[i]*dinv^2 + bias ) )
__global__ void k_gather_h(const float* __restrict__ bias, int n) {
    const int gt   = blockIdx.x * blockDim.x + threadIdx.x;
    const int node = gt >> 5;
    const int lane = gt & 31;
    if (node >= n) return;

    const uint2* hh = (const uint2*)g_hh;

    float di = g_dinv[node];
    float sl = di * di;

    uint2 selfv = hh[(long)node * 32 + lane];
    __half2 s0 = *(__half2*)&selfv.x, s1 = *(__half2*)&selfv.y;
    float2 f0 = __half22float2(s0), f1 = __half22float2(s1);
    float ax = f0.x * sl, ay = f0.y * sl, az = f1.x * sl, aw = f1.y * sl;

    const int o = g_off[node];
    const int c = g_cnt[node];
#pragma unroll 4
    for (int k = 0; k < c; k++) {
        int2 sp = g_csr[o + k];
        float nrm = __int_as_float(sp.y);
        uint2 hv = hh[(long)sp.x * 32 + lane];
        __half2 h0 = *(__half2*)&hv.x, h1 = *(__half2*)&hv.y;
        float2 g0 = __half22float2(h0), g1 = __half22float2(h1);
        ax = fmaf(g0.x, nrm, ax);
        ay = fmaf(g0.y, nrm, ay);
        az = fmaf(g1.x, nrm, az);
        aw = fmaf(g1.y, nrm, aw);
    }
    float4 bv = *(const float4*)(bias + lane * 4);
    float rx = fmaxf(ax + bv.x, 0.f);
    float ry = fmaxf(ay + bv.y, 0.f);
    float rz = fmaxf(az + bv.z, 0.f);
    float rw = fmaxf(aw + bv.w, 0.f);
    __half2 o0 = __floats2half2_rn(rx, ry), o1 = __floats2half2_rn(rz, rw);
    uint2 u; u.x = *(unsigned*)&o0; u.y = *(unsigned*)&o1;
    ((uint2*)g_a16)[(long)node * 32 + lane] = u;
}

// ---------------- sparse aggregation, fp32 (F=64, final layer) ----------------
__global__ void k_gather_f64(const float* __restrict__ bias,
                             float* __restrict__ outp, int n) {
    constexpr int LPN = 16;
    const int gt   = blockIdx.x * blockDim.x + threadIdx.x;
    const int node = gt / LPN;
    const int lane = gt % LPN;
    if (node >= n) return;

    float di = g_dinv[node];
    float sl = di * di;
    float4 acc = g_h4[(long)node * LPN + lane];
    acc.x *= sl; acc.y *= sl; acc.z *= sl; acc.w *= sl;

    const int o = g_off[node];
    const int c = g_cnt[node];
#pragma unroll 4
    for (int k = 0; k < c; k++) {
        int2 sp = g_csr[o + k];
        float nrm = __int_as_float(sp.y);
        float4 hv = g_h4[(long)sp.x * LPN + lane];
        acc.x = fmaf(hv.x, nrm, acc.x);
        acc.y = fmaf(hv.y, nrm, acc.y);
        acc.z = fmaf(hv.z, nrm, acc.z);
        acc.w = fmaf(hv.w, nrm, acc.w);
    }
    float4 bv = *(const float4*)(bias + lane * 4);
    acc.x += bv.x; acc.y += bv.y; acc.z += bv.z; acc.w += bv.w;
    *(float4*)(outp + (long)node * 64 + lane * 4) = acc;
}

// ---------------- host launcher ----------------
extern "C" void kernel_launch(void* const* d_in, const int* in_sizes, int n_in,
                              void* d_out, int out_size) {
    const float* x  = (const float*)d_in[0];
    const void*  ei = d_in[1];
    const float* ew = (const float*)d_in[2];
    const float* W1 = (const float*)d_in[3];
    const float* b1 = (const float*)d_in[4];
    const float* W2 = (const float*)d_in[5];
    const float* b2 = (const float*)d_in[6];
    const float* W3 = (const float*)d_in[7];
    const float* b3 = (const float*)d_in[8];

    const int n = in_sizes[0] / KDIM;   // 50000
    const int E = in_sizes[2];          // 1600000
    float* outp = (float*)d_out;

    const int TB = 256;
    const int nb_nodes = (n + TB - 1) / TB;
    const int nb_edges = (E + TB - 1) / TB;
    const int nchunk   = (n + 511) / 512;
    const int nprep    = (n * 16 + 5120 + TB - 1) / TB;

    // ---- setup: init+detect, conversions, degrees, scan, CSR fill ----
    k_init<<<nb_nodes, TB>>>(ei, n);
    k_prep<<<nprep, TB>>>((const float4*)x, (const float4*)W1,
                          (const float4*)W2, (const float4*)W3, n);
    k_edge_deg<<<nb_edges, TB>>>(ei, ew, E, n);
    k_scan_reduce<<<nchunk, 512>>>(n);
    k_scan_top<<<1, 32>>>(nchunk);
    k_scan_chunks<<<nchunk, 512>>>(n);
    k_edge_fill<<<nb_edges, TB>>>(ew, E);

    const int gemm_blocks   = (n + 63) / 64;
    const int gat128_blocks = (n * 32 + TB - 1) / TB;
    const int gat64_blocks  = (n * 16 + TB - 1) / TB;

    // ---- layer 1 ----
    k_hgemm<128, true><<<gemm_blocks, 256>>>(0, n);
    k_gather_h<<<gat128_blocks, TB>>>(b1, n);

    // ---- layer 2 ----
    k_hgemm<128, true><<<gemm_blocks, 256>>>(2048, n);
    k_gather_h<<<gat128_blocks, TB>>>(b2, n);

    // ---- layer 3 (fp32 out) ----
    k_hgemm<64, false><<<gemm_blocks, 256>>>(4096, n);
    k_gather_f64<<<gat64_blocks, TB>>>(b3, outp, n);
}

// round 6
// speedup vs baseline: 1.2461x; 1.0506x over previous
#include <cuda_runtime.h>
#include <cuda_fp16.h>
#include <mma.h>
using namespace nvcuda;

// ---------------- problem constants ----------------
#define NMAX 50000
#define EMAX 1600000
#define KDIM 128

// ---------------- device scratch ----------------
__device__ float  g_deg [NMAX];
__device__ float  g_dinv[NMAX];
__device__ int    g_cnt [NMAX];
__device__ int    g_off [NMAX];
__device__ int    g_pos [NMAX];
__device__ int    g_src [EMAX];
__device__ int    g_dst [EMAX];
__device__ int2   g_csr [EMAX];              // (src, norm-as-bits), bucketed by dst
__device__ int    g_bsum[256];
__device__ int    g_is64;
__device__ uint4  g_a16 [NMAX * KDIM / 8];   // fp16 activations (GEMM input)
__device__ uint4  g_hh  [NMAX * KDIM / 8];   // fp16 GEMM output (gather input)
__device__ uint4  g_w16 [5120];              // fp16 W1(2048) W2(2048) W3(1024) uint4s

// ---------------- fused init + dtype detect ----------------
__global__ void k_init(const void* __restrict__ ei, int n) {
    int i = blockIdx.x * blockDim.x + threadIdx.x;
    if (i < n) { g_deg[i] = 1.0f; g_cnt[i] = 0; }
    if (i == 0) {
        const long long* p = (const long long*)ei;
        int ok = 1;
#pragma unroll
        for (int t = 0; t < 16; t++) {
            long long v = p[t];
            if (v < 0 || v >= (long long)n) ok = 0;
        }
        g_is64 = ok;
    }
}

// ---------------- fp32 -> fp16 conversion: x and all weights ----------------
__device__ inline uint4 pack8(float4 a, float4 b) {
    __half2 h0 = __floats2half2_rn(a.x, a.y), h1 = __floats2half2_rn(a.z, a.w);
    __half2 h2 = __floats2half2_rn(b.x, b.y), h3 = __floats2half2_rn(b.z, b.w);
    uint4 u;
    u.x = *(unsigned*)&h0; u.y = *(unsigned*)&h1;
    u.z = *(unsigned*)&h2; u.w = *(unsigned*)&h3;
    return u;
}

__global__ void k_prep(const float4* __restrict__ x,
                       const float4* __restrict__ W1,
                       const float4* __restrict__ W2,
                       const float4* __restrict__ W3, int n) {
    int i = blockIdx.x * blockDim.x + threadIdx.x;
    int nx = n * 16;
    if (i < nx) {
        g_a16[i] = pack8(x[2 * i], x[2 * i + 1]);
    } else {
        int j = i - nx;
        if (j < 5120) {
            const float4* src; int jj;
            if (j < 2048)      { src = W1; jj = j; }
            else if (j < 4096) { src = W2; jj = j - 2048; }
            else               { src = W3; jj = j - 4096; }
            g_w16[j] = pack8(src[2 * jj], src[2 * jj + 1]);
        }
    }
}

// ---------------- edge pass 1: degree + counts ----------------
__global__ void k_edge_deg(const void* __restrict__ ei,
                           const float* __restrict__ ew, int E, int n) {
    int e = blockIdx.x * blockDim.x + threadIdx.x;
    if (e >= E) return;
    int s, d;
    if (g_is64) {
        const long long* p = (const long long*)ei;
        s = (int)p[e]; d = (int)p[E + e];
    } else {
        const int* p = (const int*)ei;
        s = p[e]; d = p[E + e];
    }
    if ((unsigned)s >= (unsigned)n || (unsigned)d >= (unsigned)n) { g_src[e] = 0; g_dst[e] = 0; return; }
    g_src[e] = s; g_dst[e] = d;
    atomicAdd(&g_deg[d], ew[e]);
    atomicAdd(&g_cnt[d], 1);
}

// ---------------- scan reduce (+ fused dinv) ----------------
__global__ void k_scan_reduce(int n) {
    __shared__ int s[512];
    int t = threadIdx.x, i = blockIdx.x * 512 + t;
    if (i < n) g_dinv[i] = rsqrtf(g_deg[i]);
    s[t] = (i < n) ? g_cnt[i] : 0;
    __syncthreads();
    for (int st = 256; st > 0; st >>= 1) {
        if (t < st) s[t] += s[t + st];
        __syncthreads();
    }
    if (t == 0) g_bsum[blockIdx.x] = s[0];
}

// scan within chunk + inline prefix over preceding chunk sums (no k_scan_top)
__global__ void k_scan_chunks(int n) {
    __shared__ int s[512];
    __shared__ int base;
    int t = threadIdx.x, i = blockIdx.x * 512 + t;
    if (t == 0) base = 0;
    __syncthreads();
    int partial = 0;
    for (int j = t; j < blockIdx.x; j += 512) partial += g_bsum[j];
    if (partial) atomicAdd(&base, partial);
    int v = (i < n) ? g_cnt[i] : 0;
    s[t] = v;
    __syncthreads();
    for (int st = 1; st < 512; st <<= 1) {
        int add = (t >= st) ? s[t - st] : 0;
        __syncthreads();
        s[t] += add;
        __syncthreads();
    }
    if (i < n) {
        int ex = s[t] - v + base;
        g_off[i] = ex;
        g_pos[i] = ex;
    }
}

__global__ void k_edge_fill(const float* __restrict__ ew, int E) {
    int e = blockIdx.x * blockDim.x + threadIdx.x;
    if (e >= E) return;
    int s = g_src[e], d = g_dst[e];
    float nrm = g_dinv[s] * ew[e] * g_dinv[d];
    int p = atomicAdd(&g_pos[d], 1);
    g_csr[p] = make_int2(s, __float_as_int(nrm));
}

// ---------------- tensor-core GEMM: C[M,N] = A16[M,128] @ W16[128,N] ----------------
// BM=64 rows/CTA, 8 warps (4x2), warp tile 16 x (N/2). Output always fp16 -> g_hh.
template<int N>
__global__ void __launch_bounds__(256)
k_hgemm(int woff_u4, int M) {
    constexpr int BM  = 64;
    constexpr int LDA = 136;
    constexpr int WN  = N / 2;
    constexpr int NT  = WN / 16;
    constexpr int ABYTES = BM * LDA * 2;
    constexpr int SBYTES = 8 * 16 * WN * 4;
    __shared__ __align__(16) char sraw[(ABYTES > SBYTES) ? ABYTES : SBYTES];
    __half (*As)[LDA] = (__half(*)[LDA])sraw;
    float*  stage     = (float*)sraw;

    const __half* Wg = (const __half*)g_w16 + (long)woff_u4 * 8;

    const int tid  = threadIdx.x;
    const int wid  = tid >> 5, lane = tid & 31;
    const int wrow = wid >> 1, wcol = wid & 1;
    const int rb   = blockIdx.x * BM;

    for (int i = tid; i < BM * 16; i += 256) {
        int r = i >> 4, c = i & 15;
        uint4 v = make_uint4(0u, 0u, 0u, 0u);
        if (rb + r < M) v = g_a16[(long)(rb + r) * 16 + c];
        *(uint4*)&As[r][c * 8] = v;
    }
    __syncthreads();

    wmma::fragment<wmma::accumulator, 16, 16, 16, float> acc[NT];
#pragma unroll
    for (int j = 0; j < NT; j++) wmma::fill_fragment(acc[j], 0.0f);

    wmma::fragment<wmma::matrix_a, 16, 16, 16, __half, wmma::row_major> af;
    wmma::fragment<wmma::matrix_b, 16, 16, 16, __half, wmma::row_major> bf;
#pragma unroll
    for (int k = 0; k < 8; k++) {
        wmma::load_matrix_sync(af, &As[wrow * 16][k * 16], LDA);
#pragma unroll
        for (int j = 0; j < NT; j++) {
            wmma::load_matrix_sync(bf, Wg + (long)(k * 16) * N + wcol * WN + j * 16, N);
            wmma::mma_sync(acc[j], af, bf, acc[j]);
        }
    }
    __syncthreads();

    float* st = stage + wid * 16 * WN;
#pragma unroll
    for (int j = 0; j < NT; j++)
        wmma::store_matrix_sync(st + j * 16, acc[j], WN, wmma::mem_row_major);
    __syncwarp();

    const int r0 = rb + wrow * 16;
    unsigned* outh = (unsigned*)g_hh;
    for (int i = lane; i < 16 * WN / 2; i += 32) {
        int r = (i * 2) / WN, c = (i * 2) % WN;
        int gr = r0 + r;
        if (gr < M) {
            __half2 h = __floats2half2_rn(st[r * WN + c], st[r * WN + c + 1]);
            outh[((long)gr * N + wcol * WN + c) >> 1] = *(unsigned*)&h;
        }
    }
}

// ---------------- sparse aggregation, fp16 features, F=128 ----------------
__global__ void k_gather_h(const float* __restrict__ bias, int n) {
    const int gt   = blockIdx.x * blockDim.x + threadIdx.x;
    const int node = gt >> 5;
    const int lane = gt & 31;
    if (node >= n) return;

    const uint2* hh = (const uint2*)g_hh;

    float di = g_dinv[node];
    float sl = di * di;

    uint2 selfv = hh[(long)node * 32 + lane];
    __half2 s0 = *(__half2*)&selfv.x, s1 = *(__half2*)&selfv.y;
    float2 f0 = __half22float2(s0), f1 = __half22float2(s1);
    float ax = f0.x * sl, ay = f0.y * sl, az = f1.x * sl, aw = f1.y * sl;

    const int o = g_off[node];
    const int c = g_cnt[node];
#pragma unroll 4
    for (int k = 0; k < c; k++) {
        int2 sp = g_csr[o + k];
        float nrm = __int_as_float(sp.y);
        uint2 hv = hh[(long)sp.x * 32 + lane];
        __half2 h0 = *(__half2*)&hv.x, h1 = *(__half2*)&hv.y;
        float2 g0 = __half22float2(h0), g1 = __half22float2(h1);
        ax = fmaf(g0.x, nrm, ax);
        ay = fmaf(g0.y, nrm, ay);
        az = fmaf(g1.x, nrm, az);
        aw = fmaf(g1.y, nrm, aw);
    }
    float4 bv = *(const float4*)(bias + lane * 4);
    float rx = fmaxf(ax + bv.x, 0.f);
    float ry = fmaxf(ay + bv.y, 0.f);
    float rz = fmaxf(az + bv.z, 0.f);
    float rw = fmaxf(aw + bv.w, 0.f);
    __half2 o0 = __floats2half2_rn(rx, ry), o1 = __floats2half2_rn(rz, rw);
    uint2 u; u.x = *(unsigned*)&o0; u.y = *(unsigned*)&o1;
    ((uint2*)g_a16)[(long)node * 32 + lane] = u;
}

// ---------------- sparse aggregation, fp16 features, F=64 (final, fp32 out) ----------------
__global__ void k_gather_h64(const float* __restrict__ bias,
                             float* __restrict__ outp, int n) {
    const int gt   = blockIdx.x * blockDim.x + threadIdx.x;
    const int node = gt >> 5;
    const int lane = gt & 31;        // lane handles features 2*lane, 2*lane+1
    if (node >= n) return;

    const unsigned* hh = (const unsigned*)g_hh;   // half2 units, 32 per node

    float di = g_dinv[node];
    float sl = di * di;

    unsigned selfv = hh[(long)node * 32 + lane];
    float2 f = __half22float2(*(__half2*)&selfv);
    float ax = f.x * sl, ay = f.y * sl;

    const int o = g_off[node];
    const int c = g_cnt[node];
#pragma unroll 4
    for (int k = 0; k < c; k++) {
        int2 sp = g_csr[o + k];
        float nrm = __int_as_float(sp.y);
        unsigned hv = hh[(long)sp.x * 32 + lane];
        float2 g = __half22float2(*(__half2*)&hv);
        ax = fmaf(g.x, nrm, ax);
        ay = fmaf(g.y, nrm, ay);
    }
    float2 bv = *(const float2*)(bias + lane * 2);
    float2 r = make_float2(ax + bv.x, ay + bv.y);
    *(float2*)(outp + (long)node * 64 + lane * 2) = r;
}

// ---------------- host launcher ----------------
extern "C" void kernel_launch(void* const* d_in, const int* in_sizes, int n_in,
                              void* d_out, int out_size) {
    const float* x  = (const float*)d_in[0];
    const void*  ei = d_in[1];
    const float* ew = (const float*)d_in[2];
    const float* W1 = (const float*)d_in[3];
    const float* b1 = (const float*)d_in[4];
    const float* W2 = (const float*)d_in[5];
    const float* b2 = (const float*)d_in[6];
    const float* W3 = (const float*)d_in[7];
    const float* b3 = (const float*)d_in[8];

    const int n = in_sizes[0] / KDIM;   // 50000
    const int E = in_sizes[2];          // 1600000
    float* outp = (float*)d_out;

    const int TB = 256;
    const int nb_nodes = (n + TB - 1) / TB;
    const int nb_edges = (E + TB - 1) / TB;
    const int nchunk   = (n + 511) / 512;
    const int nprep    = (n * 16 + 5120 + TB - 1) / TB;
    const int gemm_blocks   = (n + 63) / 64;
    const int gat_blocks    = (n * 32 + TB - 1) / TB;

    // ---- fork: side stream runs prep + GEMM1 concurrently with CSR build ----
    cudaStream_t s1;
    cudaStreamCreateWithFlags(&s1, cudaStreamNonBlocking);
    cudaEvent_t e0, e1;
    cudaEventCreateWithFlags(&e0, cudaEventDisableTiming);
    cudaEventCreateWithFlags(&e1, cudaEventDisableTiming);

    cudaEventRecord(e0, 0);
    cudaStreamWaitEvent(s1, e0, 0);

    // branch B (s1): fp16 conversion + layer-1 GEMM (depends only on x, W)
    k_prep<<<nprep, TB, 0, s1>>>((const float4*)x, (const float4*)W1,
                                 (const float4*)W2, (const float4*)W3, n);
    k_hgemm<128><<<gemm_blocks, 256, 0, s1>>>(0, n);

    // branch A (capture stream): CSR build
    k_init<<<nb_nodes, TB>>>(ei, n);
    k_edge_deg<<<nb_edges, TB>>>(ei, ew, E, n);
    k_scan_reduce<<<nchunk, 512>>>(n);
    k_scan_chunks<<<nchunk, 512>>>(n);
    k_edge_fill<<<nb_edges, TB>>>(ew, E);

    // join
    cudaEventRecord(e1, s1);
    cudaStreamWaitEvent(0, e1, 0);

    // ---- layer 1 gather ----
    k_gather_h<<<gat_blocks, TB>>>(b1, n);

    // ---- layer 2 ----
    k_hgemm<128><<<gemm_blocks, 256>>>(2048, n);
    k_gather_h<<<gat_blocks, TB>>>(b2, n);

    // ---- layer 3 (fp16 h, fp32 out) ----
    k_hgemm<64><<<gemm_blocks, 256>>>(4096, n);
    k_gather_h64<<<gat_blocks, TB>>>(b3, outp, n);

    cudaEventDestroy(e0);
    cudaEventDestroy(e1);
    cudaStreamDestroy(s1);
}